// round 1
// baseline (speedup 1.0000x reference)
#include <cuda_runtime.h>
#include <cuda_bf16.h>

#define TT 512
#define BB 64
#define II 256
#define HH 1024
#define OO 128

// ---------------- scratch (device globals; no allocation allowed) ----------------
static __device__ __nv_bfloat16 g_x0[TT * BB * II];   // x transposed to [T,B,I], bf16 hi
static __device__ __nv_bfloat16 g_x1[TT * BB * II];   // bf16 lo
static __device__ __nv_bfloat16 g_wih0[HH * II];
static __device__ __nv_bfloat16 g_wih1[HH * II];
static __device__ __nv_bfloat16 g_whh0[HH * HH];
static __device__ __nv_bfloat16 g_whh1[HH * HH];
static __device__ float         g_xp[(size_t)TT * BB * HH];  // precomputed input proj + biases
static __device__ float         g_part[8 * BB * HH];         // K-split partials
static __device__ __nv_bfloat16 g_h0[BB * HH];               // hidden state hi split
static __device__ __nv_bfloat16 g_h1[BB * HH];               // hidden state lo split
static __device__ unsigned      g_bar_count;
static __device__ unsigned      g_bar_sense;

// ---------------- helpers ----------------
__device__ __forceinline__ unsigned ld_acq(unsigned* p) {
    unsigned v;
    asm volatile("ld.acquire.gpu.u32 %0, [%1];" : "=r"(v) : "l"(p) : "memory");
    return v;
}
__device__ __forceinline__ void st_rel(unsigned* p, unsigned v) {
    asm volatile("st.release.gpu.u32 [%0], %1;" ::"l"(p), "r"(v) : "memory");
}

// sense-reversing grid barrier; requires all CTAs co-resident (grid <= #SM).
__device__ __forceinline__ void grid_bar(unsigned& sense, unsigned nctas) {
    __syncthreads();
    if (threadIdx.x == 0) {
        unsigned target = sense ^ 1u;
        sense = target;
        __threadfence();
        unsigned prev = atomicAdd(&g_bar_count, 1u);
        if (prev == nctas - 1u) {
            g_bar_count = 0u;
            st_rel(&g_bar_sense, target);
        } else {
            while (ld_acq(&g_bar_sense) != target) {}
        }
    }
    __syncthreads();
}

__device__ __forceinline__ void mma16816(float& d0, float& d1, float& d2, float& d3,
                                         unsigned a0, unsigned a1, unsigned a2, unsigned a3,
                                         unsigned b0, unsigned b1) {
    asm volatile(
        "mma.sync.aligned.m16n8k16.row.col.f32.bf16.bf16.f32 "
        "{%0,%1,%2,%3},{%4,%5,%6,%7},{%8,%9},{%0,%1,%2,%3};\n"
        : "+f"(d0), "+f"(d1), "+f"(d2), "+f"(d3)
        : "r"(a0), "r"(a1), "r"(a2), "r"(a3), "r"(b0), "r"(b1));
}

// copy a 64 x COLS bf16 tile (gmem, row stride src_stride elems) into smem (row stride PAD)
template <int COLS, int PAD>
__device__ __forceinline__ void copy_tile(__nv_bfloat16* dst, const __nv_bfloat16* src,
                                          int src_stride) {
    constexpr int U4R = COLS / 8;       // uint4 per row
    constexpr int TOT = 64 * U4R;
#pragma unroll 4
    for (int it = threadIdx.x; it < TOT; it += 256) {
        int r = it / U4R;
        int c = (it % U4R) * 8;
        *reinterpret_cast<uint4*>(dst + r * PAD + c) =
            *reinterpret_cast<const uint4*>(src + r * src_stride + c);
    }
}

// ---------------- split kernels (precision: fp32 -> bf16 hi/lo) ----------------
__global__ void split_x_kernel(const float* __restrict__ x) {
    int i = blockIdx.x * 256 + threadIdx.x;            // index into [T][B][I] output
    int ii = i & (II - 1);
    int tb = i >> 8;
    int b = tb & (BB - 1);
    int t = tb >> 6;
    float v = x[((size_t)(b * TT + t) << 8) + ii];     // x is [B][T][I]
    __nv_bfloat16 h = __float2bfloat16(v);
    g_x0[i] = h;
    g_x1[i] = __float2bfloat16(v - __bfloat162float(h));
}

__global__ void split_wih_kernel(const float* __restrict__ w) {
    int i = blockIdx.x * 256 + threadIdx.x;
    float v = w[i];
    __nv_bfloat16 h = __float2bfloat16(v);
    g_wih0[i] = h;
    g_wih1[i] = __float2bfloat16(v - __bfloat162float(h));
}

__global__ void split_whh_kernel(const float* __restrict__ w) {
    int i = blockIdx.x * 256 + threadIdx.x;
    float v = w[i];
    __nv_bfloat16 h = __float2bfloat16(v);
    g_whh0[i] = h;
    g_whh1[i] = __float2bfloat16(v - __bfloat162float(h));
}

__global__ void zero_h_kernel() {
    int i = blockIdx.x * 256 + threadIdx.x;
    __nv_bfloat16 z = __float2bfloat16(0.0f);
    g_h0[i] = z;
    g_h1[i] = z;
}

// ---------------- phase 1: xp = x @ W_ih^T + b_ih + b_hh  (bf16x3) ----------------
// grid (512, 16): blockIdx.x = M-tile (one t, 64 batches), blockIdx.y = N-tile (64 hidden)
__global__ void __launch_bounds__(256, 1)
xp_gemm_kernel(const float* __restrict__ b_ih, const float* __restrict__ b_hh) {
    extern __shared__ __align__(16) unsigned char smem_raw[];
    __nv_bfloat16* sx0 = reinterpret_cast<__nv_bfloat16*>(smem_raw);   // 64 x 264
    __nv_bfloat16* sx1 = sx0 + 64 * 264;
    __nv_bfloat16* sw0 = sx1 + 64 * 264;
    __nv_bfloat16* sw1 = sw0 + 64 * 264;

    const int mt = blockIdx.x;
    const int nt = blockIdx.y;

    copy_tile<256, 264>(sx0, g_x0 + (size_t)(mt * 64) * II, II);
    copy_tile<256, 264>(sx1, g_x1 + (size_t)(mt * 64) * II, II);
    copy_tile<256, 264>(sw0, g_wih0 + (size_t)(nt * 64) * II, II);
    copy_tile<256, 264>(sw1, g_wih1 + (size_t)(nt * 64) * II, II);
    __syncthreads();

    const int warp = threadIdx.x >> 5, lane = threadIdx.x & 31;
    const int m0 = (warp >> 1) << 4;   // 0..48
    const int n0 = (warp & 1) << 5;    // 0 / 32
    const int gr = lane >> 2;
    const int qc = (lane & 3) << 1;

    float d[4][4] = {};
#pragma unroll
    for (int seg = 0; seg < 3; ++seg) {
        const __nv_bfloat16* A = (seg < 2) ? sx0 : sx1;
        const __nv_bfloat16* Bm = (seg == 1) ? sw1 : sw0;
        const __nv_bfloat16* ar = A + (m0 + gr) * 264 + qc;
#pragma unroll 4
        for (int kk = 0; kk < 256; kk += 16) {
            unsigned a0 = *reinterpret_cast<const unsigned*>(ar + kk);
            unsigned a1 = *reinterpret_cast<const unsigned*>(ar + kk + 8 * 264);
            unsigned a2 = *reinterpret_cast<const unsigned*>(ar + kk + 8);
            unsigned a3 = *reinterpret_cast<const unsigned*>(ar + kk + 8 * 264 + 8);
#pragma unroll
            for (int nj = 0; nj < 4; ++nj) {
                const __nv_bfloat16* bp = Bm + (n0 + nj * 8 + gr) * 264 + kk + qc;
                unsigned b0 = *reinterpret_cast<const unsigned*>(bp);
                unsigned b1 = *reinterpret_cast<const unsigned*>(bp + 8);
                mma16816(d[nj][0], d[nj][1], d[nj][2], d[nj][3], a0, a1, a2, a3, b0, b1);
            }
        }
    }

    const int rowg = mt * 64 + m0 + gr;
    const int colg = nt * 64 + n0 + qc;
#pragma unroll
    for (int nj = 0; nj < 4; ++nj) {
        int c0 = colg + nj * 8;
        float bs0 = b_ih[c0] + b_hh[c0];
        float bs1 = b_ih[c0 + 1] + b_hh[c0 + 1];
        *reinterpret_cast<float2*>(g_xp + (size_t)rowg * HH + c0) =
            make_float2(d[nj][0] + bs0, d[nj][1] + bs1);
        *reinterpret_cast<float2*>(g_xp + (size_t)(rowg + 8) * HH + c0) =
            make_float2(d[nj][2] + bs0, d[nj][3] + bs1);
    }
}

// ---------------- phase 2: persistent scan over T=512 ----------------
// 128 CTAs = 16 N-tiles x 8 K-splits. W_hh tiles stay in SMEM for all steps.
// Per step: stage A (mma partials) -> barrier -> stage B (reduce + tanh + re-split) -> barrier.
__global__ void __launch_bounds__(256, 1) rnn_scan_kernel() {
    extern __shared__ __align__(16) unsigned char smem_raw[];
    __nv_bfloat16* sw0 = reinterpret_cast<__nv_bfloat16*>(smem_raw);   // 64 x 136
    __nv_bfloat16* sw1 = sw0 + 64 * 136;
    __nv_bfloat16* sa0 = sw1 + 64 * 136;
    __nv_bfloat16* sa1 = sa0 + 64 * 136;

    const int ntile = blockIdx.x & 15;
    const int ks = blockIdx.x >> 4;

    // resident weight tiles: rows j = ntile*64.., cols k = ks*128..
    copy_tile<128, 136>(sw0, g_whh0 + (size_t)(ntile * 64) * HH + ks * 128, HH);
    copy_tile<128, 136>(sw1, g_whh1 + (size_t)(ntile * 64) * HH + ks * 128, HH);

    unsigned sense = 0;
    if (threadIdx.x == 0) sense = ld_acq(&g_bar_sense);  // survive graph replays

    const int warp = threadIdx.x >> 5, lane = threadIdx.x & 31;
    const int m0 = (warp >> 1) << 4;
    const int n0 = (warp & 1) << 5;
    const int gr = lane >> 2;
    const int qc = (lane & 3) << 1;

    for (int t = 0; t < TT; ++t) {
        // stage A: load h-chunk, compute partial P = h0*W0 + h0*W1 + h1*W0 over k-window
        copy_tile<128, 136>(sa0, g_h0 + ks * 128, HH);
        copy_tile<128, 136>(sa1, g_h1 + ks * 128, HH);
        __syncthreads();

        float d[4][4] = {};
#pragma unroll
        for (int seg = 0; seg < 3; ++seg) {
            const __nv_bfloat16* A = (seg < 2) ? sa0 : sa1;
            const __nv_bfloat16* Bm = (seg == 1) ? sw1 : sw0;
            const __nv_bfloat16* ar = A + (m0 + gr) * 136 + qc;
#pragma unroll
            for (int kk = 0; kk < 128; kk += 16) {
                unsigned a0 = *reinterpret_cast<const unsigned*>(ar + kk);
                unsigned a1 = *reinterpret_cast<const unsigned*>(ar + kk + 8 * 136);
                unsigned a2 = *reinterpret_cast<const unsigned*>(ar + kk + 8);
                unsigned a3 = *reinterpret_cast<const unsigned*>(ar + kk + 8 * 136 + 8);
#pragma unroll
                for (int nj = 0; nj < 4; ++nj) {
                    const __nv_bfloat16* bp = Bm + (n0 + nj * 8 + gr) * 136 + kk + qc;
                    unsigned b0 = *reinterpret_cast<const unsigned*>(bp);
                    unsigned b1 = *reinterpret_cast<const unsigned*>(bp + 8);
                    mma16816(d[nj][0], d[nj][1], d[nj][2], d[nj][3], a0, a1, a2, a3, b0, b1);
                }
            }
        }

        float* Pp = g_part + ks * (BB * HH) + (m0 + gr) * HH + ntile * 64 + n0 + qc;
#pragma unroll
        for (int nj = 0; nj < 4; ++nj) {
            *reinterpret_cast<float2*>(Pp + nj * 8) = make_float2(d[nj][0], d[nj][1]);
            *reinterpret_cast<float2*>(Pp + nj * 8 + 8 * HH) = make_float2(d[nj][2], d[nj][3]);
        }

        grid_bar(sense, 128);

        // stage B: h_new = tanh(xp_t + sum_ks P); re-split to bf16 hi/lo
        {
            const int base = blockIdx.x * 512 + threadIdx.x * 2;
            float2 acc = *reinterpret_cast<const float2*>(g_xp + (size_t)t * (BB * HH) + base);
#pragma unroll
            for (int s = 0; s < 8; ++s) {
                float2 p = *reinterpret_cast<const float2*>(g_part + s * (BB * HH) + base);
                acc.x += p.x;
                acc.y += p.y;
            }
            float hx = tanhf(acc.x), hy = tanhf(acc.y);
            __nv_bfloat16 hx0 = __float2bfloat16(hx);
            __nv_bfloat16 hy0 = __float2bfloat16(hy);
            __nv_bfloat162 v0;
            v0.x = hx0;
            v0.y = hy0;
            *reinterpret_cast<__nv_bfloat162*>(g_h0 + base) = v0;
            __nv_bfloat162 v1;
            v1.x = __float2bfloat16(hx - __bfloat162float(hx0));
            v1.y = __float2bfloat16(hy - __bfloat162float(hy0));
            *reinterpret_cast<__nv_bfloat162*>(g_h1 + base) = v1;
        }

        grid_bar(sense, 128);
    }
}

// ---------------- phase 3: out = h_last @ W_lin^T + b_lin ----------------
__global__ void final_linear_kernel(const float* __restrict__ wlin,
                                    const float* __restrict__ blin,
                                    float* __restrict__ out) {
    int gw = (blockIdx.x * 256 + threadIdx.x) >> 5;   // one warp per output
    int lane = threadIdx.x & 31;
    int b = gw >> 7;
    int o = gw & (OO - 1);
    const float* wr = wlin + (size_t)o * HH;
    float sum = 0.0f;
#pragma unroll 8
    for (int k = lane; k < HH; k += 32) {
        float hv = __bfloat162float(g_h0[b * HH + k]) + __bfloat162float(g_h1[b * HH + k]);
        sum += hv * wr[k];
    }
#pragma unroll
    for (int off = 16; off > 0; off >>= 1) sum += __shfl_down_sync(0xffffffffu, sum, off);
    if (lane == 0) out[b * OO + o] = sum + blin[o];
}

// ---------------- launch ----------------
extern "C" void kernel_launch(void* const* d_in, const int* in_sizes, int n_in,
                              void* d_out, int out_size) {
    (void)in_sizes; (void)n_in; (void)out_size;
    const float* x     = (const float*)d_in[0];
    const float* W_ih  = (const float*)d_in[1];
    const float* W_hh  = (const float*)d_in[2];
    const float* b_ih  = (const float*)d_in[3];
    const float* b_hh  = (const float*)d_in[4];
    const float* W_lin = (const float*)d_in[5];
    const float* b_lin = (const float*)d_in[6];
    float* out = (float*)d_out;

    cudaFuncSetAttribute(xp_gemm_kernel, cudaFuncAttributeMaxDynamicSharedMemorySize,
                         4 * 64 * 264 * 2);
    cudaFuncSetAttribute(rnn_scan_kernel, cudaFuncAttributeMaxDynamicSharedMemorySize,
                         4 * 64 * 136 * 2);

    split_x_kernel<<<(TT * BB * II) / 256, 256>>>(x);
    split_wih_kernel<<<(HH * II) / 256, 256>>>(W_ih);
    split_whh_kernel<<<(HH * HH) / 256, 256>>>(W_hh);
    zero_h_kernel<<<(BB * HH) / 256, 256>>>();

    xp_gemm_kernel<<<dim3(512, 16), 256, 4 * 64 * 264 * 2>>>(b_ih, b_hh);
    rnn_scan_kernel<<<128, 256, 4 * 64 * 136 * 2>>>();
    final_linear_kernel<<<(BB * OO * 32) / 256, 256>>>(W_lin, b_lin, out);
}

// round 3
// speedup vs baseline: 1.0748x; 1.0748x over previous
#include <cuda_runtime.h>
#include <cuda_bf16.h>
#include <cstdint>

#define TT 512
#define BB 64
#define II 256
#define HH 1024
#define OO 128
#define NCTA 128   // scan grid: 16 n-tiles x 8 k-splits

// ---------------- scratch (device globals; no allocation allowed) ----------------
static __device__ __nv_bfloat16 g_x0[TT * BB * II];   // x transposed to [T,B,I], bf16 hi
static __device__ __nv_bfloat16 g_x1[TT * BB * II];   // bf16 lo
static __device__ __nv_bfloat16 g_wih0[HH * II];
static __device__ __nv_bfloat16 g_wih1[HH * II];
static __device__ __nv_bfloat16 g_whh0[HH * HH];
static __device__ __nv_bfloat16 g_whh1[HH * HH];
static __device__ float         g_xp[(size_t)TT * BB * HH];  // input proj + biases, [t][b][h]
static __device__ float         g_part[8 * BB * HH];         // K-split partials [ks][b][h]
static __device__ __nv_bfloat16 g_h0[BB * HH];               // hidden hi split [b][h]
static __device__ __nv_bfloat16 g_h1[BB * HH];               // hidden lo split
static __device__ unsigned      g_bar_count;
static __device__ unsigned      g_bar_sense;

// ---------------- helpers ----------------
__device__ __forceinline__ unsigned ld_acq(unsigned* p) {
    unsigned v;
    asm volatile("ld.acquire.gpu.u32 %0, [%1];" : "=r"(v) : "l"(p) : "memory");
    return v;
}
__device__ __forceinline__ void st_rel(unsigned* p, unsigned v) {
    asm volatile("st.release.gpu.u32 [%0], %1;" ::"l"(p), "r"(v) : "memory");
}

// sense-reversing grid barrier; release-arrive + acquire-spin (no full membar).
__device__ __forceinline__ void grid_bar(unsigned& sense, unsigned nctas) {
    __syncthreads();
    if (threadIdx.x == 0) {
        unsigned target = sense ^ 1u;
        sense = target;
        unsigned prev;
        asm volatile("atom.add.release.gpu.global.u32 %0, [%1], 1;"
                     : "=r"(prev) : "l"(&g_bar_count) : "memory");
        if (prev == nctas - 1u) {
            g_bar_count = 0u;
            st_rel(&g_bar_sense, target);
        } else {
            while (ld_acq(&g_bar_sense) != target) {}
        }
    }
    __syncthreads();
}

__device__ __forceinline__ uint32_t smem_u32(const void* p) {
    uint32_t a;
    asm("{ .reg .u64 t; cvta.to.shared.u64 t, %1; cvt.u32.u64 %0, t; }" : "=r"(a) : "l"(p));
    return a;
}

__device__ __forceinline__ void mma16816(float& d0, float& d1, float& d2, float& d3,
                                         unsigned a0, unsigned a1, unsigned a2, unsigned a3,
                                         unsigned b0, unsigned b1) {
    asm volatile(
        "mma.sync.aligned.m16n8k16.row.col.f32.bf16.bf16.f32 "
        "{%0,%1,%2,%3},{%4,%5,%6,%7},{%8,%9},{%0,%1,%2,%3};\n"
        : "+f"(d0), "+f"(d1), "+f"(d2), "+f"(d3)
        : "r"(a0), "r"(a1), "r"(a2), "r"(a3), "r"(b0), "r"(b1));
}

__device__ __forceinline__ void ldsm_x4(unsigned& r0, unsigned& r1, unsigned& r2, unsigned& r3,
                                        uint32_t addr) {
    asm volatile("ldmatrix.sync.aligned.m8n8.x4.shared.b16 {%0,%1,%2,%3}, [%4];"
                 : "=r"(r0), "=r"(r1), "=r"(r2), "=r"(r3) : "r"(addr));
}

__device__ __forceinline__ void cp16(uint32_t dst, const void* src) {
    asm volatile("cp.async.ca.shared.global [%0], [%1], 16;" ::"r"(dst), "l"(src) : "memory");
}

template <int COLS, int PAD>
__device__ __forceinline__ void copy_tile(__nv_bfloat16* dst, const __nv_bfloat16* src,
                                          int src_stride) {
    constexpr int U4R = COLS / 8;
    constexpr int TOT = 64 * U4R;
#pragma unroll 4
    for (int it = threadIdx.x; it < TOT; it += 256) {
        int r = it / U4R;
        int c = (it % U4R) * 8;
        *reinterpret_cast<uint4*>(dst + r * PAD + c) =
            *reinterpret_cast<const uint4*>(src + r * src_stride + c);
    }
}

// ---------------- split kernels ----------------
__global__ void split_x_kernel(const float* __restrict__ x) {
    int i = blockIdx.x * 256 + threadIdx.x;
    int ii = i & (II - 1);
    int tb = i >> 8;
    int b = tb & (BB - 1);
    int t = tb >> 6;
    float v = x[((size_t)(b * TT + t) << 8) + ii];
    __nv_bfloat16 h = __float2bfloat16(v);
    g_x0[i] = h;
    g_x1[i] = __float2bfloat16(v - __bfloat162float(h));
}

__global__ void split_wih_kernel(const float* __restrict__ w) {
    int i = blockIdx.x * 256 + threadIdx.x;
    float v = w[i];
    __nv_bfloat16 h = __float2bfloat16(v);
    g_wih0[i] = h;
    g_wih1[i] = __float2bfloat16(v - __bfloat162float(h));
}

__global__ void split_whh_kernel(const float* __restrict__ w) {
    int i = blockIdx.x * 256 + threadIdx.x;
    float v = w[i];
    __nv_bfloat16 h = __float2bfloat16(v);
    g_whh0[i] = h;
    g_whh1[i] = __float2bfloat16(v - __bfloat162float(h));
}

__global__ void zero_h_kernel() {
    int i = blockIdx.x * 256 + threadIdx.x;
    __nv_bfloat16 z = __float2bfloat16(0.0f);
    g_h0[i] = z;
    g_h1[i] = z;
}

// ---------------- phase 1: xp = x @ W_ih^T + b_ih + b_hh  (bf16x3 mma.sync) ----------------
__global__ void __launch_bounds__(256, 1)
xp_gemm_kernel(const float* __restrict__ b_ih, const float* __restrict__ b_hh) {
    extern __shared__ __align__(16) unsigned char smem_raw[];
    __nv_bfloat16* sx0 = reinterpret_cast<__nv_bfloat16*>(smem_raw);
    __nv_bfloat16* sx1 = sx0 + 64 * 264;
    __nv_bfloat16* sw0 = sx1 + 64 * 264;
    __nv_bfloat16* sw1 = sw0 + 64 * 264;

    const int mt = blockIdx.x;
    const int nt = blockIdx.y;

    copy_tile<256, 264>(sx0, g_x0 + (size_t)(mt * 64) * II, II);
    copy_tile<256, 264>(sx1, g_x1 + (size_t)(mt * 64) * II, II);
    copy_tile<256, 264>(sw0, g_wih0 + (size_t)(nt * 64) * II, II);
    copy_tile<256, 264>(sw1, g_wih1 + (size_t)(nt * 64) * II, II);
    __syncthreads();

    const int warp = threadIdx.x >> 5, lane = threadIdx.x & 31;
    const int m0 = (warp >> 1) << 4;
    const int n0 = (warp & 1) << 5;
    const int gr = lane >> 2;
    const int qc = (lane & 3) << 1;

    float d[4][4] = {};
#pragma unroll
    for (int seg = 0; seg < 3; ++seg) {
        const __nv_bfloat16* A = (seg < 2) ? sx0 : sx1;
        const __nv_bfloat16* Bm = (seg == 1) ? sw1 : sw0;
        const __nv_bfloat16* ar = A + (m0 + gr) * 264 + qc;
#pragma unroll 4
        for (int kk = 0; kk < 256; kk += 16) {
            unsigned a0 = *reinterpret_cast<const unsigned*>(ar + kk);
            unsigned a1 = *reinterpret_cast<const unsigned*>(ar + kk + 8 * 264);
            unsigned a2 = *reinterpret_cast<const unsigned*>(ar + kk + 8);
            unsigned a3 = *reinterpret_cast<const unsigned*>(ar + kk + 8 * 264 + 8);
#pragma unroll
            for (int nj = 0; nj < 4; ++nj) {
                const __nv_bfloat16* bp = Bm + (n0 + nj * 8 + gr) * 264 + kk + qc;
                unsigned b0 = *reinterpret_cast<const unsigned*>(bp);
                unsigned b1 = *reinterpret_cast<const unsigned*>(bp + 8);
                mma16816(d[nj][0], d[nj][1], d[nj][2], d[nj][3], a0, a1, a2, a3, b0, b1);
            }
        }
    }

    const int rowg = mt * 64 + m0 + gr;
    const int colg = nt * 64 + n0 + qc;
#pragma unroll
    for (int nj = 0; nj < 4; ++nj) {
        int c0 = colg + nj * 8;
        float bs0 = b_ih[c0] + b_hh[c0];
        float bs1 = b_ih[c0 + 1] + b_hh[c0 + 1];
        *reinterpret_cast<float2*>(g_xp + (size_t)rowg * HH + c0) =
            make_float2(d[nj][0] + bs0, d[nj][1] + bs1);
        *reinterpret_cast<float2*>(g_xp + (size_t)(rowg + 8) * HH + c0) =
            make_float2(d[nj][2] + bs0, d[nj][3] + bs1);
    }
}

// ---------------- phase 2: persistent scan (HMMA + ldmatrix + cp.async) ----------------
// 128 CTAs = 16 ntile (64 hidden cols) x 8 ks (128-wide k window).
// Per step: cp.async h tiles -> 96 mma (bf16x3) -> store partials -> barrier
//           -> reduce + tanh + re-split h -> barrier.
__global__ void __launch_bounds__(256, 1) rnn_scan_kernel() {
    extern __shared__ __align__(16) unsigned char smem_raw[];
    __nv_bfloat16* sw0 = reinterpret_cast<__nv_bfloat16*>(smem_raw);   // W tiles 64 x 136
    __nv_bfloat16* sw1 = sw0 + 64 * 136;
    __nv_bfloat16* sa0 = sw1 + 64 * 136;                               // h tiles 64 x 136
    __nv_bfloat16* sa1 = sa0 + 64 * 136;

    const int tid = threadIdx.x;
    const int ntile = blockIdx.x & 15;
    const int ks = blockIdx.x >> 4;

    // resident weight tiles: rows j = ntile*64.., cols k = ks*128..
    copy_tile<128, 136>(sw0, g_whh0 + (size_t)(ntile * 64) * HH + ks * 128, HH);
    copy_tile<128, 136>(sw1, g_whh1 + (size_t)(ntile * 64) * HH + ks * 128, HH);

    const int warp = tid >> 5, lane = tid & 31;
    const int m0 = (warp >> 1) << 4;   // batch row group 0..48
    const int n0 = (warp & 1) << 5;    // hidden col group 0 / 32
    const int gr = lane >> 2;
    const int qc = (lane & 3) << 1;

    // ldmatrix per-lane base byte offsets (row stride = 136*2 = 272 bytes)
    const uint32_t a_off = (uint32_t)((m0 + (lane & 15)) * 272 + (lane >> 4) * 16);
    const uint32_t b_off0 = (uint32_t)((n0 + ((lane >> 4) << 3) + (lane & 7)) * 272 +
                                       ((lane >> 3) & 1) * 16);
    const uint32_t b_off1 = b_off0 + 16 * 272;

    const uint32_t uA0 = smem_u32(sa0), uA1 = smem_u32(sa1);
    const uint32_t uW0 = smem_u32(sw0), uW1 = smem_u32(sw1);

    // cp.async destinations for the h tiles
    const __nv_bfloat16* gh0 = g_h0 + ks * 128;
    const __nv_bfloat16* gh1 = g_h1 + ks * 128;

    unsigned sense = 0;   // 1024 flips per run -> returns to 0; safe across graph replays

    for (int t = 0; t < TT; ++t) {
        // ---- stage A: async-copy h chunk (64 x 128 x 2 splits) ----
#pragma unroll
        for (int i = 0; i < 4; ++i) {
            int it = tid + i * 256;           // 0..1023
            int r = it >> 4;
            int c = it & 15;
            uint32_t d0 = uA0 + r * 272 + c * 16;
            uint32_t d1 = uA1 + r * 272 + c * 16;
            const __nv_bfloat16* s0 = gh0 + (size_t)r * HH + c * 8;
            const __nv_bfloat16* s1 = gh1 + (size_t)r * HH + c * 8;
            cp16(d0, s0);
            cp16(d1, s1);
        }
        asm volatile("cp.async.commit_group;" ::: "memory");
        // prefetch xp for stage B while copies drain
        float2 acc = *reinterpret_cast<const float2*>(
            g_xp + (size_t)t * (BB * HH) + blockIdx.x * 512 + tid * 2);
        asm volatile("cp.async.wait_group 0;" ::: "memory");
        __syncthreads();

        float d[4][4] = {};
#pragma unroll
        for (int seg = 0; seg < 3; ++seg) {
            const uint32_t ab = (seg < 2) ? uA0 : uA1;
            const uint32_t wb = (seg == 1) ? uW1 : uW0;
#pragma unroll
            for (int kk = 0; kk < 8; ++kk) {
                unsigned a0, a1, a2, a3, p0, p1, p2, p3, q0, q1, q2, q3;
                ldsm_x4(a0, a1, a2, a3, ab + a_off + kk * 32);
                ldsm_x4(p0, p1, p2, p3, wb + b_off0 + kk * 32);
                ldsm_x4(q0, q1, q2, q3, wb + b_off1 + kk * 32);
                mma16816(d[0][0], d[0][1], d[0][2], d[0][3], a0, a1, a2, a3, p0, p1);
                mma16816(d[1][0], d[1][1], d[1][2], d[1][3], a0, a1, a2, a3, p2, p3);
                mma16816(d[2][0], d[2][1], d[2][2], d[2][3], a0, a1, a2, a3, q0, q1);
                mma16816(d[3][0], d[3][1], d[3][2], d[3][3], a0, a1, a2, a3, q2, q3);
            }
        }

        // store partials [ks][b][h]
        float* Pp = g_part + ks * (BB * HH) + (m0 + gr) * HH + ntile * 64 + n0 + qc;
#pragma unroll
        for (int nj = 0; nj < 4; ++nj) {
            *reinterpret_cast<float2*>(Pp + nj * 8) = make_float2(d[nj][0], d[nj][1]);
            *reinterpret_cast<float2*>(Pp + nj * 8 + 8 * HH) = make_float2(d[nj][2], d[nj][3]);
        }

        grid_bar(sense, NCTA);

        // ---- stage B: h = tanh(xp + sum partials); re-split ----
        {
            const int base = blockIdx.x * 512 + tid * 2;
#pragma unroll
            for (int s = 0; s < 8; ++s) {
                float2 p = *reinterpret_cast<const float2*>(g_part + (size_t)s * (BB * HH) + base);
                acc.x += p.x;
                acc.y += p.y;
            }
            float hx = tanhf(acc.x), hy = tanhf(acc.y);
            __nv_bfloat162 v0;
            v0.x = __float2bfloat16(hx);
            v0.y = __float2bfloat16(hy);
            *reinterpret_cast<__nv_bfloat162*>(g_h0 + base) = v0;
            __nv_bfloat162 v1;
            v1.x = __float2bfloat16(hx - __bfloat162float(v0.x));
            v1.y = __float2bfloat16(hy - __bfloat162float(v0.y));
            *reinterpret_cast<__nv_bfloat162*>(g_h1 + base) = v1;
        }

        grid_bar(sense, NCTA);
    }
}

// ---------------- phase 3: out = h_last @ W_lin^T + b_lin ----------------
__global__ void final_linear_kernel(const float* __restrict__ wlin,
                                    const float* __restrict__ blin,
                                    float* __restrict__ out) {
    int gw = (blockIdx.x * 256 + threadIdx.x) >> 5;
    int lane = threadIdx.x & 31;
    int b = gw >> 7;
    int o = gw & (OO - 1);
    const float* wr = wlin + (size_t)o * HH;
    float sum = 0.0f;
#pragma unroll 8
    for (int k = lane; k < HH; k += 32) {
        float hv = __bfloat162float(g_h0[b * HH + k]) + __bfloat162float(g_h1[b * HH + k]);
        sum += hv * wr[k];
    }
#pragma unroll
    for (int off = 16; off > 0; off >>= 1) sum += __shfl_down_sync(0xffffffffu, sum, off);
    if (lane == 0) out[b * OO + o] = sum + blin[o];
}

// ---------------- launch ----------------
extern "C" void kernel_launch(void* const* d_in, const int* in_sizes, int n_in,
                              void* d_out, int out_size) {
    (void)in_sizes; (void)n_in; (void)out_size;
    const float* x     = (const float*)d_in[0];
    const float* W_ih  = (const float*)d_in[1];
    const float* W_hh  = (const float*)d_in[2];
    const float* b_ih  = (const float*)d_in[3];
    const float* b_hh  = (const float*)d_in[4];
    const float* W_lin = (const float*)d_in[5];
    const float* b_lin = (const float*)d_in[6];
    float* out = (float*)d_out;

    cudaFuncSetAttribute(xp_gemm_kernel, cudaFuncAttributeMaxDynamicSharedMemorySize,
                         4 * 64 * 264 * 2);
    cudaFuncSetAttribute(rnn_scan_kernel, cudaFuncAttributeMaxDynamicSharedMemorySize,
                         4 * 64 * 136 * 2);

    split_x_kernel<<<(TT * BB * II) / 256, 256>>>(x);
    split_wih_kernel<<<(HH * II) / 256, 256>>>(W_ih);
    split_whh_kernel<<<(HH * HH) / 256, 256>>>(W_hh);
    zero_h_kernel<<<(BB * HH) / 256, 256>>>();

    xp_gemm_kernel<<<dim3(512, 16), 256, 4 * 64 * 264 * 2>>>(b_ih, b_hh);
    rnn_scan_kernel<<<NCTA, 256, 4 * 64 * 136 * 2>>>();
    final_linear_kernel<<<(BB * OO * 32) / 256, 256>>>(W_lin, b_lin, out);
}

// round 4
// speedup vs baseline: 1.2358x; 1.1498x over previous
#include <cuda_runtime.h>
#include <cuda_bf16.h>
#include <cstdint>

#define TT 512
#define BB 64
#define II 256
#define HH 1024
#define OO 128
#define NCTA 128   // scan grid: 16 nt-groups x 8 k-splits

// ---------------- scratch (device globals; no allocation allowed) ----------------
static __device__ __nv_bfloat16 g_x0[TT * BB * II];   // x [T,B,I], bf16 hi
static __device__ __nv_bfloat16 g_x1[TT * BB * II];   // bf16 lo
static __device__ __nv_bfloat16 g_wih0[HH * II];
static __device__ __nv_bfloat16 g_wih1[HH * II];
static __device__ __nv_bfloat16 g_whh0[HH * HH];
static __device__ __nv_bfloat16 g_whh1[HH * HH];
static __device__ float         g_xp[(size_t)TT * BB * HH];  // [t][j][b]  (transposed!)
static __device__ float         g_part[2 * 8 * BB * HH];     // [parity][ks][j][b]
static __device__ __nv_bfloat16 g_h0[3 * BB * HH];           // h hi, [buf][k][b]
static __device__ __nv_bfloat16 g_h1[3 * BB * HH];           // h lo
static __device__ float         g_hT[BB * HH];               // h_512, [b][k] for final linear
static __device__ unsigned      g_flagA[NCTA * 8];           // padded 32B per flag
static __device__ unsigned      g_flagB[NCTA * 8];

// ---------------- helpers ----------------
__device__ __forceinline__ unsigned ld_acq(const unsigned* p) {
    unsigned v;
    asm volatile("ld.acquire.gpu.u32 %0, [%1];" : "=r"(v) : "l"(p) : "memory");
    return v;
}
__device__ __forceinline__ void st_rel(unsigned* p, unsigned v) {
    asm volatile("st.release.gpu.u32 [%0], %1;" ::"l"(p), "r"(v) : "memory");
}

__device__ __forceinline__ uint32_t smem_u32(const void* p) {
    uint32_t a;
    asm("{ .reg .u64 t; cvta.to.shared.u64 t, %1; cvt.u32.u64 %0, t; }" : "=r"(a) : "l"(p));
    return a;
}

__device__ __forceinline__ void mma16816(float& d0, float& d1, float& d2, float& d3,
                                         unsigned a0, unsigned a1, unsigned a2, unsigned a3,
                                         unsigned b0, unsigned b1) {
    asm volatile(
        "mma.sync.aligned.m16n8k16.row.col.f32.bf16.bf16.f32 "
        "{%0,%1,%2,%3},{%4,%5,%6,%7},{%8,%9},{%0,%1,%2,%3};\n"
        : "+f"(d0), "+f"(d1), "+f"(d2), "+f"(d3)
        : "r"(a0), "r"(a1), "r"(a2), "r"(a3), "r"(b0), "r"(b1));
}

__device__ __forceinline__ void ldsm_x4(unsigned& r0, unsigned& r1, unsigned& r2, unsigned& r3,
                                        uint32_t addr) {
    asm volatile("ldmatrix.sync.aligned.m8n8.x4.shared.b16 {%0,%1,%2,%3}, [%4];"
                 : "=r"(r0), "=r"(r1), "=r"(r2), "=r"(r3) : "r"(addr));
}
__device__ __forceinline__ void ldsm_x4t(unsigned& r0, unsigned& r1, unsigned& r2, unsigned& r3,
                                         uint32_t addr) {
    asm volatile("ldmatrix.sync.aligned.m8n8.x4.trans.shared.b16 {%0,%1,%2,%3}, [%4];"
                 : "=r"(r0), "=r"(r1), "=r"(r2), "=r"(r3) : "r"(addr));
}

__device__ __forceinline__ void cp16(uint32_t dst, const void* src) {
    asm volatile("cp.async.ca.shared.global [%0], [%1], 16;" ::"r"(dst), "l"(src) : "memory");
}

template <int COLS, int PAD>
__device__ __forceinline__ void copy_tile(__nv_bfloat16* dst, const __nv_bfloat16* src,
                                          int src_stride) {
    constexpr int U4R = COLS / 8;
    constexpr int TOT = 64 * U4R;
#pragma unroll 4
    for (int it = threadIdx.x; it < TOT; it += 256) {
        int r = it / U4R;
        int c = (it % U4R) * 8;
        *reinterpret_cast<uint4*>(dst + r * PAD + c) =
            *reinterpret_cast<const uint4*>(src + r * src_stride + c);
    }
}

// ---------------- split / init kernels ----------------
__global__ void split_x_kernel(const float* __restrict__ x) {
    int i = blockIdx.x * 256 + threadIdx.x;
    int ii = i & (II - 1);
    int tb = i >> 8;
    int b = tb & (BB - 1);
    int t = tb >> 6;
    float v = x[((size_t)(b * TT + t) << 8) + ii];
    __nv_bfloat16 h = __float2bfloat16(v);
    g_x0[i] = h;
    g_x1[i] = __float2bfloat16(v - __bfloat162float(h));
}

__global__ void split_wih_kernel(const float* __restrict__ w) {
    int i = blockIdx.x * 256 + threadIdx.x;
    float v = w[i];
    __nv_bfloat16 h = __float2bfloat16(v);
    g_wih0[i] = h;
    g_wih1[i] = __float2bfloat16(v - __bfloat162float(h));
}

__global__ void split_whh_kernel(const float* __restrict__ w) {
    int i = blockIdx.x * 256 + threadIdx.x;
    float v = w[i];
    __nv_bfloat16 h = __float2bfloat16(v);
    g_whh0[i] = h;
    g_whh1[i] = __float2bfloat16(v - __bfloat162float(h));
}

__global__ void init_kernel() {
    int i = blockIdx.x * 256 + threadIdx.x;   // 65536 threads
    __nv_bfloat16 z = __float2bfloat16(0.0f);
    g_h0[i] = z;        // buffer 0 (= h_0 state)
    g_h1[i] = z;
    if (i < NCTA * 8) {
        g_flagA[i] = 0u;
        g_flagB[i] = 0u;
    }
}

// ---------------- phase 1: xp[t][j][b] = (x @ W_ih^T + b_ih + b_hh)^T ----------------
__global__ void __launch_bounds__(256, 1)
xp_gemm_kernel(const float* __restrict__ b_ih, const float* __restrict__ b_hh) {
    extern __shared__ __align__(16) unsigned char smem_raw[];
    __nv_bfloat16* sx0 = reinterpret_cast<__nv_bfloat16*>(smem_raw);
    __nv_bfloat16* sx1 = sx0 + 64 * 264;
    __nv_bfloat16* sw0 = sx1 + 64 * 264;
    __nv_bfloat16* sw1 = sw0 + 64 * 264;

    const int mt = blockIdx.x;   // = t (64 batch rows)
    const int nt = blockIdx.y;   // hidden tile

    copy_tile<256, 264>(sx0, g_x0 + (size_t)(mt * 64) * II, II);
    copy_tile<256, 264>(sx1, g_x1 + (size_t)(mt * 64) * II, II);
    copy_tile<256, 264>(sw0, g_wih0 + (size_t)(nt * 64) * II, II);
    copy_tile<256, 264>(sw1, g_wih1 + (size_t)(nt * 64) * II, II);
    __syncthreads();

    const int warp = threadIdx.x >> 5, lane = threadIdx.x & 31;
    const int m0 = (warp >> 1) << 4;
    const int n0 = (warp & 1) << 5;
    const int gr = lane >> 2;
    const int qc = (lane & 3) << 1;

    float d[4][4] = {};
#pragma unroll
    for (int seg = 0; seg < 3; ++seg) {
        const __nv_bfloat16* A = (seg < 2) ? sx0 : sx1;
        const __nv_bfloat16* Bm = (seg == 1) ? sw1 : sw0;
        const __nv_bfloat16* ar = A + (m0 + gr) * 264 + qc;
#pragma unroll 4
        for (int kk = 0; kk < 256; kk += 16) {
            unsigned a0 = *reinterpret_cast<const unsigned*>(ar + kk);
            unsigned a1 = *reinterpret_cast<const unsigned*>(ar + kk + 8 * 264);
            unsigned a2 = *reinterpret_cast<const unsigned*>(ar + kk + 8);
            unsigned a3 = *reinterpret_cast<const unsigned*>(ar + kk + 8 * 264 + 8);
#pragma unroll
            for (int nj = 0; nj < 4; ++nj) {
                const __nv_bfloat16* bp = Bm + (n0 + nj * 8 + gr) * 264 + kk + qc;
                unsigned b0 = *reinterpret_cast<const unsigned*>(bp);
                unsigned b1 = *reinterpret_cast<const unsigned*>(bp + 8);
                mma16816(d[nj][0], d[nj][1], d[nj][2], d[nj][3], a0, a1, a2, a3, b0, b1);
            }
        }
    }

    // transposed store: xp[t=mt][j][b]
    const int bb = m0 + gr;
    const int colg = nt * 64 + n0 + qc;
    float* outb = g_xp + (size_t)mt * (BB * HH);
#pragma unroll
    for (int nj = 0; nj < 4; ++nj) {
        int j = colg + nj * 8;
        float bsA = b_ih[j] + b_hh[j];
        float bsB = b_ih[j + 1] + b_hh[j + 1];
        outb[(size_t)j * 64 + bb] = d[nj][0] + bsA;
        outb[(size_t)(j + 1) * 64 + bb] = d[nj][1] + bsB;
        outb[(size_t)j * 64 + bb + 8] = d[nj][2] + bsA;
        outb[(size_t)(j + 1) * 64 + bb + 8] = d[nj][3] + bsB;
    }
}

// ---------------- phase 2: persistent scan, point-to-point flag sync ----------------
// CTA bid: GEMM role (nt = bid>>3 : j-rows nt*64..+64 ; ks = bid&7 : k-window ks*128..+128)
//          Reduce role (slice = 8 j-rows x 64 b at bid*512)
// Flags: flagA[bid]  = partials(step t) ready        (consumers: 8 CTAs of nt-group)
//        flagB[bid]  = h slice(step t+1) ready       (consumers: 16 CTAs with matching ks)
__global__ void __launch_bounds__(256, 1) rnn_scan_kernel() {
    extern __shared__ __align__(16) unsigned char smem_raw[];
    __nv_bfloat16* sw0 = reinterpret_cast<__nv_bfloat16*>(smem_raw);       // 64 x 136 (W0)
    __nv_bfloat16* sw1 = sw0 + 64 * 136;                                   // (W1)
    __nv_bfloat16* sh0 = sw1 + 64 * 136;   // h0 tile: 128 k-rows x 72 (144B rows)
    __nv_bfloat16* sh1 = sh0 + 128 * 72;   // h1 tile

    const int tid = threadIdx.x;
    const int bid = blockIdx.x;
    const int nt = bid >> 3;
    const int ks = bid & 7;

    // resident W tiles (A-operand): rows j = nt*64.., cols k = ks*128..
    copy_tile<128, 136>(sw0, g_whh0 + (size_t)(nt * 64) * HH + ks * 128, HH);
    copy_tile<128, 136>(sw1, g_whh1 + (size_t)(nt * 64) * HH + ks * 128, HH);
    __syncthreads();

    const int warp = tid >> 5, lane = tid & 31;
    const int m0 = (warp >> 1) << 4;   // j sub-tile
    const int n0 = (warp & 1) << 5;    // b half
    const int gr = lane >> 2;
    const int qc = (lane & 3) << 1;

    // hoist W fragments into registers for all 512 steps
    const uint32_t uW0 = smem_u32(sw0), uW1 = smem_u32(sw1);
    const uint32_t a_off = (uint32_t)((m0 + (lane & 15)) * 272 + (lane >> 4) * 16);
    unsigned W0f[8][4], W1f[8][4];
#pragma unroll
    for (int kk = 0; kk < 8; ++kk) {
        ldsm_x4(W0f[kk][0], W0f[kk][1], W0f[kk][2], W0f[kk][3], uW0 + a_off + kk * 32);
        ldsm_x4(W1f[kk][0], W1f[kk][1], W1f[kk][2], W1f[kk][3], uW1 + a_off + kk * 32);
    }

    const uint32_t uH0 = smem_u32(sh0), uH1 = smem_u32(sh1);
    const uint32_t hb_off = (uint32_t)((lane & 15) * 144 + ((lane >> 4) * 8 + n0) * 2);

    unsigned* const fA_my = g_flagA + bid * 8;
    unsigned* const fB_my = g_flagB + bid * 8;
    const unsigned* const fB_poll = g_flagB + (ks * 16 + (tid & 15)) * 8;
    const unsigned* const fA_poll = g_flagA + (nt * 8 + (tid & 7)) * 8;
    const int slice = bid * 512 + tid * 2;

    for (int t = 0; t < TT; ++t) {
        const unsigned p = (unsigned)(t & 1);

        // ---- wait h_t (16 producer flags; trivially satisfied at t=0) ----
        if (tid < 16) {
            while (ld_acq(fB_poll) != p) {}
        }
        __syncthreads();

        // ---- async-load h tiles from buffer t%3, rows k = ks*128..+128 ----
        const __nv_bfloat16* hb0 = g_h0 + (t % 3) * (BB * HH) + ks * 128 * 64;
        const __nv_bfloat16* hb1 = g_h1 + (t % 3) * (BB * HH) + ks * 128 * 64;
#pragma unroll
        for (int i = 0; i < 4; ++i) {
            int it = tid + i * 256;
            int r = it >> 3, c = it & 7;
            cp16(uH0 + r * 144 + c * 16, hb0 + r * 64 + c * 8);
            cp16(uH1 + r * 144 + c * 16, hb1 + r * 64 + c * 8);
        }
        asm volatile("cp.async.commit_group;" ::: "memory");
        // prefetch xp[t] slice for reduce stage
        float2 acc = *reinterpret_cast<const float2*>(g_xp + (size_t)t * (BB * HH) + slice);
        asm volatile("cp.async.wait_group 0;" ::: "memory");
        __syncthreads();

        // ---- MMA: D[j16 x b32] += W0*h0 + W1*h0 + W0*h1 ----
        float d[4][4] = {};
#pragma unroll
        for (int kk = 0; kk < 8; ++kk) {
            unsigned r0, r1, r2, r3, s0, s1, s2, s3;
            ldsm_x4t(r0, r1, r2, r3, uH0 + hb_off + kk * 2304);
            ldsm_x4t(s0, s1, s2, s3, uH0 + hb_off + kk * 2304 + 32);
            mma16816(d[0][0], d[0][1], d[0][2], d[0][3],
                     W0f[kk][0], W0f[kk][1], W0f[kk][2], W0f[kk][3], r0, r1);
            mma16816(d[1][0], d[1][1], d[1][2], d[1][3],
                     W0f[kk][0], W0f[kk][1], W0f[kk][2], W0f[kk][3], r2, r3);
            mma16816(d[2][0], d[2][1], d[2][2], d[2][3],
                     W0f[kk][0], W0f[kk][1], W0f[kk][2], W0f[kk][3], s0, s1);
            mma16816(d[3][0], d[3][1], d[3][2], d[3][3],
                     W0f[kk][0], W0f[kk][1], W0f[kk][2], W0f[kk][3], s2, s3);
            mma16816(d[0][0], d[0][1], d[0][2], d[0][3],
                     W1f[kk][0], W1f[kk][1], W1f[kk][2], W1f[kk][3], r0, r1);
            mma16816(d[1][0], d[1][1], d[1][2], d[1][3],
                     W1f[kk][0], W1f[kk][1], W1f[kk][2], W1f[kk][3], r2, r3);
            mma16816(d[2][0], d[2][1], d[2][2], d[2][3],
                     W1f[kk][0], W1f[kk][1], W1f[kk][2], W1f[kk][3], s0, s1);
            mma16816(d[3][0], d[3][1], d[3][2], d[3][3],
                     W1f[kk][0], W1f[kk][1], W1f[kk][2], W1f[kk][3], s2, s3);
        }
#pragma unroll
        for (int kk = 0; kk < 8; ++kk) {
            unsigned r0, r1, r2, r3, s0, s1, s2, s3;
            ldsm_x4t(r0, r1, r2, r3, uH1 + hb_off + kk * 2304);
            ldsm_x4t(s0, s1, s2, s3, uH1 + hb_off + kk * 2304 + 32);
            mma16816(d[0][0], d[0][1], d[0][2], d[0][3],
                     W0f[kk][0], W0f[kk][1], W0f[kk][2], W0f[kk][3], r0, r1);
            mma16816(d[1][0], d[1][1], d[1][2], d[1][3],
                     W0f[kk][0], W0f[kk][1], W0f[kk][2], W0f[kk][3], r2, r3);
            mma16816(d[2][0], d[2][1], d[2][2], d[2][3],
                     W0f[kk][0], W0f[kk][1], W0f[kk][2], W0f[kk][3], s0, s1);
            mma16816(d[3][0], d[3][1], d[3][2], d[3][3],
                     W0f[kk][0], W0f[kk][1], W0f[kk][2], W0f[kk][3], s2, s3);
        }

        // ---- store partials [parity][ks][j][b] ----
        float* Pp = g_part + ((size_t)p * 8 + ks) * (BB * HH) +
                    (size_t)(nt * 64 + m0 + gr) * 64 + n0 + qc;
#pragma unroll
        for (int nj = 0; nj < 4; ++nj) {
            *reinterpret_cast<float2*>(Pp + nj * 8) = make_float2(d[nj][0], d[nj][1]);
            *reinterpret_cast<float2*>(Pp + nj * 8 + 8 * 64) = make_float2(d[nj][2], d[nj][3]);
        }
        __syncthreads();
        if (tid == 0) st_rel(fA_my, p ^ 1u);

        // ---- wait partials of my nt-group (8 flags, includes own) ----
        if (tid < 8) {
            while (ld_acq(fA_poll) != (p ^ 1u)) {}
        }
        __syncthreads();

        // ---- reduce + tanh + split; write h_{t+1} into buffer (t+1)%3 ----
        {
            float sx = acc.x, sy = acc.y;
#pragma unroll
            for (int s = 0; s < 8; ++s) {
                float2 q = *reinterpret_cast<const float2*>(
                    g_part + ((size_t)p * 8 + s) * (BB * HH) + slice);
                sx += q.x;
                sy += q.y;
            }
            float hx = tanhf(sx), hy = tanhf(sy);
            int ob = ((t + 1) % 3) * (BB * HH) + slice;
            __nv_bfloat162 v0;
            v0.x = __float2bfloat16(hx);
            v0.y = __float2bfloat16(hy);
            *reinterpret_cast<__nv_bfloat162*>(g_h0 + ob) = v0;
            __nv_bfloat162 v1;
            v1.x = __float2bfloat16(hx - __bfloat162float(v0.x));
            v1.y = __float2bfloat16(hy - __bfloat162float(v0.y));
            *reinterpret_cast<__nv_bfloat162*>(g_h1 + ob) = v1;
            if (t == TT - 1) {   // also store h_512 transposed [b][k] in f32
                int j = slice >> 6, b = slice & 63;
                g_hT[(size_t)b * HH + j] = hx;
                g_hT[(size_t)(b + 1) * HH + j] = hy;
            }
        }
        __syncthreads();
        if (tid == 0) st_rel(fB_my, p ^ 1u);
    }
}

// ---------------- phase 3: out = h_last @ W_lin^T + b_lin ----------------
__global__ void final_linear_kernel(const float* __restrict__ wlin,
                                    const float* __restrict__ blin,
                                    float* __restrict__ out) {
    int gw = (blockIdx.x * 256 + threadIdx.x) >> 5;
    int lane = threadIdx.x & 31;
    int b = gw >> 7;
    int o = gw & (OO - 1);
    const float* wr = wlin + (size_t)o * HH;
    const float* hr = g_hT + (size_t)b * HH;
    float sum = 0.0f;
#pragma unroll 8
    for (int k = lane; k < HH; k += 32) sum += hr[k] * wr[k];
#pragma unroll
    for (int off = 16; off > 0; off >>= 1) sum += __shfl_down_sync(0xffffffffu, sum, off);
    if (lane == 0) out[b * OO + o] = sum + blin[o];
}

// ---------------- launch ----------------
extern "C" void kernel_launch(void* const* d_in, const int* in_sizes, int n_in,
                              void* d_out, int out_size) {
    (void)in_sizes; (void)n_in; (void)out_size;
    const float* x     = (const float*)d_in[0];
    const float* W_ih  = (const float*)d_in[1];
    const float* W_hh  = (const float*)d_in[2];
    const float* b_ih  = (const float*)d_in[3];
    const float* b_hh  = (const float*)d_in[4];
    const float* W_lin = (const float*)d_in[5];
    const float* b_lin = (const float*)d_in[6];
    float* out = (float*)d_out;

    const int scan_smem = (2 * 64 * 136 + 2 * 128 * 72) * 2;   // 71680 bytes
    cudaFuncSetAttribute(xp_gemm_kernel, cudaFuncAttributeMaxDynamicSharedMemorySize,
                         4 * 64 * 264 * 2);
    cudaFuncSetAttribute(rnn_scan_kernel, cudaFuncAttributeMaxDynamicSharedMemorySize,
                         scan_smem);

    split_x_kernel<<<(TT * BB * II) / 256, 256>>>(x);
    split_wih_kernel<<<(HH * II) / 256, 256>>>(W_ih);
    split_whh_kernel<<<(HH * HH) / 256, 256>>>(W_hh);
    init_kernel<<<(BB * HH) / 256, 256>>>();

    xp_gemm_kernel<<<dim3(512, 16), 256, 4 * 64 * 264 * 2>>>(b_ih, b_hh);
    rnn_scan_kernel<<<NCTA, 256, scan_smem>>>();
    final_linear_kernel<<<(BB * OO * 32) / 256, 256>>>(W_lin, b_lin, out);
}